// round 10
// baseline (speedup 1.0000x reference)
#include <cuda_runtime.h>
#include <cstdint>

#define BATCH 8
#define SEQ   2048
#define EMB   1024
#define HEAD  64
#define NTOK  (BATCH*SEQ)   // 16384
#define LOG2E 1.4426950408889634f
#define QSCALE (0.03125f * LOG2E)   // C^-0.5 * log2(e)

// ---------------------------------------------------------------------------
// PTX helpers (family-portable only)
// ---------------------------------------------------------------------------
__device__ __forceinline__ float tf32r(float x) {
    float y; asm("cvt.rna.tf32.f32 %0, %1;" : "=f"(y) : "f"(x)); return y;
}
__device__ __forceinline__ void mma_tf32(float* d, const uint32_t* a, const uint32_t* b) {
    asm volatile(
        "mma.sync.aligned.m16n8k8.row.col.f32.tf32.tf32.f32 "
        "{%0,%1,%2,%3}, {%4,%5,%6,%7}, {%8,%9}, {%0,%1,%2,%3};"
        : "+f"(d[0]), "+f"(d[1]), "+f"(d[2]), "+f"(d[3])
        : "r"(a[0]), "r"(a[1]), "r"(a[2]), "r"(a[3]), "r"(b[0]), "r"(b[1]));
}
__device__ __forceinline__ uint32_t s32(const void* p) {
    return (uint32_t)__cvta_generic_to_shared(p);
}
#define CP_ASYNC16(dst, src) \
    asm volatile("cp.async.cg.shared.global [%0], [%1], 16;" :: "r"(dst), "l"(src))
#define CP_COMMIT() asm volatile("cp.async.commit_group;" ::: "memory")
#define CP_WAIT0()  asm volatile("cp.async.wait_group 0;" ::: "memory")

// ---------------------------------------------------------------------------
// device scratch (Q pre-scaled; Q,K,V tf32-rounded at production)
// ---------------------------------------------------------------------------
__device__ float g_Q[NTOK*HEAD];
__device__ float g_K[NTOK*HEAD];
__device__ float g_V[NTOK*HEAD];

// ---------------------------------------------------------------------------
// Kernel 1: QKV projection, mma.sync tf32, cp.async double-buffered.
// Raw fp32 staged via cp.async; tf32 rounding applied at fragment build
// (same round points -> numerics identical).  One barrier per K-tile.
// M-tile 128, K-tile 64, grid 128, 256 threads = 8 warps (4m x 2n).
// smem: Xb[2] 128x68 | Wb[2] 3x64x68 = 43520 floats = 174080 B
// ---------------------------------------------------------------------------
#define QKV_SMEM_BYTES (43520 * 4)

__global__ __launch_bounds__(256, 1) void qkv_mma(
    const float* __restrict__ X,
    const float* __restrict__ Wq,
    const float* __restrict__ Wk,
    const float* __restrict__ Wv)
{
    extern __shared__ float qsm[];
    float* Xb[2] = { qsm,         qsm + 8704 };            // [m][k] pitch 68
    float* Wb[2] = { qsm + 17408, qsm + 17408 + 13056 };   // [w][k][n] pitch 68

    const int tid  = threadIdx.x;
    const int wid  = tid >> 5;
    const int lane = tid & 31;
    const int mw   = wid >> 1;        // 0..3 (32 m-rows)
    const int nw   = wid & 1;         // 0..1 (32 n-cols)
    const int m0   = blockIdx.x * 128;
    const int r = lane >> 2;
    const int c = lane & 3;

    const float* Wsrc[3] = { Wq, Wk, Wv };

    float acc[3][2][4][4];
    #pragma unroll
    for (int w = 0; w < 3; w++)
        #pragma unroll
        for (int mf = 0; mf < 2; mf++)
            #pragma unroll
            for (int nf = 0; nf < 4; nf++)
                #pragma unroll
                for (int e = 0; e < 4; e++) acc[w][mf][nf][e] = 0.f;

    // prologue: stage K-tile 0 into buf 0 (raw)
    #pragma unroll
    for (int it = 0; it < 8; it++) {
        int f = tid + it * 256, cc = f & 15, rr = f >> 4;
        CP_ASYNC16(s32(&Xb[0][rr*68 + 4*cc]), &X[(size_t)(m0 + rr) * EMB + 4*cc]);
    }
    #pragma unroll
    for (int it = 0; it < 12; it++) {
        int f = tid + it * 256, w = f >> 10, rem = f & 1023;
        int cc = rem & 15, rr = rem >> 4;
        CP_ASYNC16(s32(&Wb[0][w*4352 + rr*68 + 4*cc]),
                   &Wsrc[w][(size_t)rr * HEAD + 4*cc]);
    }
    CP_COMMIT();

    for (int kt = 0; kt < 16; kt++) {          // 16 K-tiles of 64
        CP_WAIT0();
        __syncthreads();   // tile kt visible; all warps done with tile kt-2 buf

        if (kt + 1 < 16) {                     // prefetch kt+1 (overlaps mma)
            float* Xn = Xb[(kt + 1) & 1];
            float* Wn = Wb[(kt + 1) & 1];
            #pragma unroll
            for (int it = 0; it < 8; it++) {
                int f = tid + it * 256, cc = f & 15, rr = f >> 4;
                CP_ASYNC16(s32(&Xn[rr*68 + 4*cc]),
                           &X[(size_t)(m0 + rr) * EMB + (kt+1)*64 + 4*cc]);
            }
            #pragma unroll
            for (int it = 0; it < 12; it++) {
                int f = tid + it * 256, w = f >> 10, rem = f & 1023;
                int cc = rem & 15, rr = rem >> 4;
                CP_ASYNC16(s32(&Wn[w*4352 + rr*68 + 4*cc]),
                           &Wsrc[w][(size_t)((kt+1)*64 + rr) * HEAD + 4*cc]);
            }
            CP_COMMIT();
        }

        const float* Xs = Xb[kt & 1];
        const float* Ws = Wb[kt & 1];
        #pragma unroll
        for (int ks = 0; ks < 8; ks++) {
            const int k = ks * 8;
            uint32_t a[2][4];
            #pragma unroll
            for (int mf = 0; mf < 2; mf++) {
                const int m = mw*32 + mf*16;
                a[mf][0] = __float_as_uint(tf32r(Xs[(m + r    )*68 + k + c    ]));
                a[mf][1] = __float_as_uint(tf32r(Xs[(m + r + 8)*68 + k + c    ]));
                a[mf][2] = __float_as_uint(tf32r(Xs[(m + r    )*68 + k + c + 4]));
                a[mf][3] = __float_as_uint(tf32r(Xs[(m + r + 8)*68 + k + c + 4]));
            }
            #pragma unroll
            for (int w = 0; w < 3; w++) {
                uint32_t b[4][2];
                #pragma unroll
                for (int nf = 0; nf < 4; nf++) {
                    const int n = nw*32 + nf*8;
                    b[nf][0] = __float_as_uint(tf32r(Ws[w*4352 + (k + c    )*68 + n + r]));
                    b[nf][1] = __float_as_uint(tf32r(Ws[w*4352 + (k + c + 4)*68 + n + r]));
                }
                #pragma unroll
                for (int mf = 0; mf < 2; mf++)
                    #pragma unroll
                    for (int nf = 0; nf < 4; nf++)
                        mma_tf32(acc[w][mf][nf], a[mf], b[nf]);
            }
        }
    }

    // epilogue: Q pre-scaled; all tf32-rounded for the attention kernel
    #pragma unroll
    for (int w = 0; w < 3; w++) {
        float* Out = (w == 0) ? g_Q : (w == 1) ? g_K : g_V;
        const float sc = (w == 0) ? QSCALE : 1.f;
        #pragma unroll
        for (int mf = 0; mf < 2; mf++) {
            const int mrow = m0 + mw*32 + mf*16 + r;
            #pragma unroll
            for (int nf = 0; nf < 4; nf++) {
                const int n = nw*32 + nf*8 + 2*c;
                *(float2*)&Out[(size_t)mrow * HEAD + n] =
                    make_float2(tf32r(acc[w][mf][nf][0] * sc),
                                tf32r(acc[w][mf][nf][1] * sc));
                *(float2*)&Out[(size_t)(mrow + 8) * HEAD + n] =
                    make_float2(tf32r(acc[w][mf][nf][2] * sc),
                                tf32r(acc[w][mf][nf][3] * sc));
            }
        }
    }
}

// ---------------------------------------------------------------------------
// Kernel 2: flash attention, mma.sync tf32, kv-tile 256, K/V prefetch.
// q-tile 64, pairs {p, 31-p} -> exactly 9 kv-tiles of 256 per CTA.
// grid (16, 8) = 128 CTAs, 256 threads = 8 warps (4m x 2n).
// Ps has its own region (no alias) so K(kt+1) can prefetch into Ks during
// softmax+PV; V(kt+1) prefetches after PV (barrier C).
// smem: Qs 4352 | Ks 17408 | Vs 17408 | Ps 64x260=16640 | red 256
// = 56064 floats = 224256 B (fits 227KB opt-in)
// ---------------------------------------------------------------------------
#define ATTN_SMEM_BYTES (56064 * 4)

__global__ __launch_bounds__(256, 1) void attn_mma(float* __restrict__ out)
{
    extern __shared__ float sm[];
    float* Qs = sm;                  // pitch 68
    float* Ks = sm + 4352;           // pitch 68, 256 rows
    float* Vs = sm + 21760;          // pitch 68, 256 rows
    float* Ps = sm + 39168;          // pitch 260, 64 rows
    float* redmax = sm + 55808;      // [2][64]
    float* redsum = redmax + 128;    // [2][64]

    const int tid  = threadIdx.x;
    const int wid  = tid >> 5;
    const int lane = tid & 31;
    const int mw   = wid >> 1;        // 0..3 (16 q-rows)
    const int nw   = wid & 1;         // 0..1 (128 keys / 32 head-cols)
    const int r    = lane >> 2;
    const int c    = lane & 3;
    const int b    = blockIdx.y;

    const float* Qg = g_Q + (size_t)b * SEQ * HEAD;
    const float* Kg = g_K + (size_t)b * SEQ * HEAD;
    const float* Vg = g_V + (size_t)b * SEQ * HEAD;

    const int rowbase = mw*16 + r;

    #pragma unroll 1
    for (int half = 0; half < 2; half++) {
        const int qb = half ? (31 - (int)blockIdx.x) : (int)blockIdx.x;
        const int q0 = qb * 64;
        const int ntiles = q0 / 256 + 1;

        // prologue: stage Q + K(0) + V(0)
        #pragma unroll
        for (int it = 0; it < 4; it++) {
            int f = tid + it * 256, cc = f & 15, rr = f >> 4;
            CP_ASYNC16(s32(&Qs[rr*68 + 4*cc]),
                       &Qg[(size_t)(q0 + rr) * HEAD + 4*cc]);
        }
        #pragma unroll
        for (int it = 0; it < 16; it++) {
            int f = tid + it * 256, cc = f & 15, rr = f >> 4;
            CP_ASYNC16(s32(&Ks[rr*68 + 4*cc]), &Kg[(size_t)rr * HEAD + 4*cc]);
            CP_ASYNC16(s32(&Vs[rr*68 + 4*cc]), &Vg[(size_t)rr * HEAD + 4*cc]);
        }
        CP_COMMIT();

        float m_st[2] = { -1e30f, -1e30f };
        float l_st[2] = { 0.f, 0.f };
        float o[4][4];
        #pragma unroll
        for (int nf = 0; nf < 4; nf++)
            #pragma unroll
            for (int e = 0; e < 4; e++) o[nf][e] = 0.f;

        for (int kt = 0; kt < ntiles; kt++) {
            const int k0 = kt * 256;
            CP_WAIT0();
            __syncthreads();   // K(kt), V(kt) (and Q) visible CTA-wide

            // ----- S = Q K^T : warp tile 16q x 128keys -----
            float s[16][4];
            #pragma unroll
            for (int nf = 0; nf < 16; nf++)
                #pragma unroll
                for (int e = 0; e < 4; e++) s[nf][e] = 0.f;

            #pragma unroll
            for (int ks = 0; ks < 8; ks++) {
                const int k = ks * 8;
                uint32_t a[4];
                a[0] = __float_as_uint(Qs[(mw*16 + r    )*68 + k + c    ]);
                a[1] = __float_as_uint(Qs[(mw*16 + r + 8)*68 + k + c    ]);
                a[2] = __float_as_uint(Qs[(mw*16 + r    )*68 + k + c + 4]);
                a[3] = __float_as_uint(Qs[(mw*16 + r + 8)*68 + k + c + 4]);
                #pragma unroll
                for (int nf = 0; nf < 16; nf++) {
                    const int n = nw*128 + nf*8;
                    uint32_t bb[2];
                    bb[0] = __float_as_uint(Ks[(n + r)*68 + k + c    ]);
                    bb[1] = __float_as_uint(Ks[(n + r)*68 + k + c + 4]);
                    mma_tf32(s[nf], a, bb);
                }
            }

            // ----- causal mask -----
            const int row0 = q0 + mw*16 + r;
            const int row1 = row0 + 8;
            if (k0 + 255 > q0) {
                #pragma unroll
                for (int nf = 0; nf < 16; nf++) {
                    const int col = k0 + nw*128 + nf*8 + 2*c;
                    if (col     > row0) s[nf][0] = -1e30f;
                    if (col + 1 > row0) s[nf][1] = -1e30f;
                    if (col     > row1) s[nf][2] = -1e30f;
                    if (col + 1 > row1) s[nf][3] = -1e30f;
                }
            }

            // ----- row max: intra-warp over c, 2-way cross-warp via smem ---
            float pm0 = s[0][0], pm1 = s[0][2];
            #pragma unroll
            for (int nf = 0; nf < 16; nf++) {
                pm0 = fmaxf(pm0, fmaxf(s[nf][0], s[nf][1]));
                pm1 = fmaxf(pm1, fmaxf(s[nf][2], s[nf][3]));
            }
            #pragma unroll
            for (int off = 1; off <= 2; off <<= 1) {
                pm0 = fmaxf(pm0, __shfl_xor_sync(0xffffffffu, pm0, off));
                pm1 = fmaxf(pm1, __shfl_xor_sync(0xffffffffu, pm1, off));
            }
            if (c == 0) {
                redmax[nw*64 + rowbase    ] = pm0;
                redmax[nw*64 + rowbase + 8] = pm1;
            }
            __syncthreads();   // (A) QK reads of Ks complete CTA-wide

            // prefetch K(kt+1) into Ks — flies under softmax + PV
            if (kt + 1 < ntiles) {
                const int kn = (kt + 1) * 256;
                #pragma unroll
                for (int it = 0; it < 16; it++) {
                    int f = tid + it * 256, cc = f & 15, rr = f >> 4;
                    CP_ASYNC16(s32(&Ks[rr*68 + 4*cc]),
                               &Kg[(size_t)(kn + rr) * HEAD + 4*cc]);
                }
                CP_COMMIT();
            }

            float mn0 = fmaxf(m_st[0], fmaxf(redmax[rowbase    ], redmax[64 + rowbase    ]));
            float mn1 = fmaxf(m_st[1], fmaxf(redmax[rowbase + 8], redmax[64 + rowbase + 8]));
            float corr0 = exp2f(m_st[0] - mn0);
            float corr1 = exp2f(m_st[1] - mn1);
            m_st[0] = mn0; m_st[1] = mn1;

            float rs0 = 0.f, rs1 = 0.f;
            #pragma unroll
            for (int nf = 0; nf < 16; nf++) {
                float p0 = exp2f(s[nf][0] - mn0);
                float p1 = exp2f(s[nf][1] - mn0);
                float p2 = exp2f(s[nf][2] - mn1);
                float p3 = exp2f(s[nf][3] - mn1);
                rs0 += p0 + p1;
                rs1 += p2 + p3;
                const int col = nw*128 + nf*8 + 2*c;
                *(float2*)&Ps[(rowbase    )*260 + col] =
                    make_float2(tf32r(p0), tf32r(p1));
                *(float2*)&Ps[(rowbase + 8)*260 + col] =
                    make_float2(tf32r(p2), tf32r(p3));
            }
            #pragma unroll
            for (int off = 1; off <= 2; off <<= 1) {
                rs0 += __shfl_xor_sync(0xffffffffu, rs0, off);
                rs1 += __shfl_xor_sync(0xffffffffu, rs1, off);
            }
            if (c == 0) {
                redsum[nw*64 + rowbase    ] = rs0;
                redsum[nw*64 + rowbase + 8] = rs1;
            }
            __syncthreads();   // (B) P + redsum visible

            l_st[0] = l_st[0] * corr0 + redsum[rowbase    ] + redsum[64 + rowbase    ];
            l_st[1] = l_st[1] * corr1 + redsum[rowbase + 8] + redsum[64 + rowbase + 8];

            #pragma unroll
            for (int nf = 0; nf < 4; nf++) {
                o[nf][0] *= corr0; o[nf][1] *= corr0;
                o[nf][2] *= corr1; o[nf][3] *= corr1;
            }

            // ----- O += P V : warp tile 16q x 32head, 32 k-steps -----
            #pragma unroll
            for (int ks = 0; ks < 32; ks++) {
                const int k = ks * 8;
                uint32_t a[4];
                a[0] = __float_as_uint(Ps[(mw*16 + r    )*260 + k + c    ]);
                a[1] = __float_as_uint(Ps[(mw*16 + r + 8)*260 + k + c    ]);
                a[2] = __float_as_uint(Ps[(mw*16 + r    )*260 + k + c + 4]);
                a[3] = __float_as_uint(Ps[(mw*16 + r + 8)*260 + k + c + 4]);
                #pragma unroll
                for (int nf = 0; nf < 4; nf++) {
                    const int n = nw*32 + nf*8;
                    uint32_t bb[2];
                    bb[0] = __float_as_uint(Vs[(k + c    )*68 + n + r]);
                    bb[1] = __float_as_uint(Vs[(k + c + 4)*68 + n + r]);
                    mma_tf32(o[nf], a, bb);
                }
            }

            // (C) PV reads of Vs complete -> prefetch V(kt+1)
            if (kt + 1 < ntiles) {
                __syncthreads();
                const int kn = (kt + 1) * 256;
                #pragma unroll
                for (int it = 0; it < 16; it++) {
                    int f = tid + it * 256, cc = f & 15, rr = f >> 4;
                    CP_ASYNC16(s32(&Vs[rr*68 + 4*cc]),
                               &Vg[(size_t)(kn + rr) * HEAD + 4*cc]);
                }
                CP_COMMIT();
            }
        }

        // epilogue: normalize, store
        const int row0 = q0 + mw*16 + r;
        const float inv0 = 1.f / l_st[0];
        const float inv1 = 1.f / l_st[1];
        #pragma unroll
        for (int nf = 0; nf < 4; nf++) {
            const int n = nw*32 + nf*8 + 2*c;
            *(float2*)&out[((size_t)b * SEQ + row0) * HEAD + n] =
                make_float2(o[nf][0] * inv0, o[nf][1] * inv0);
            *(float2*)&out[((size_t)b * SEQ + row0 + 8) * HEAD + n] =
                make_float2(o[nf][2] * inv1, o[nf][3] * inv1);
        }
        __syncthreads();   // all smem reads done before next half restages
    }
}

// ---------------------------------------------------------------------------
extern "C" void kernel_launch(void* const* d_in, const int* in_sizes, int n_in,
                              void* d_out, int out_size)
{
    const float* X  = (const float*)d_in[0];
    const float* Wq = (const float*)d_in[1];
    const float* Wk = (const float*)d_in[2];
    const float* Wv = (const float*)d_in[3];
    float* out = (float*)d_out;

    cudaFuncSetAttribute(qkv_mma,
                         cudaFuncAttributeMaxDynamicSharedMemorySize, QKV_SMEM_BYTES);
    cudaFuncSetAttribute(attn_mma,
                         cudaFuncAttributeMaxDynamicSharedMemorySize, ATTN_SMEM_BYTES);

    qkv_mma<<<128, 256, QKV_SMEM_BYTES>>>(X, Wq, Wk, Wv);

    dim3 g2(16, BATCH);
    attn_mma<<<g2, 256, ATTN_SMEM_BYTES>>>(out);
}